// round 15
// baseline (speedup 1.0000x reference)
#include <cuda_runtime.h>
#include <cuda_bf16.h>
#include <cstdint>

#define NN 100000
#define KK 4
#define EE 1600000
#define HH 64
#define FF 256
#define CHUNKS 98   // ceil(N/1024)

// ---------------- scratch (device globals; no runtime alloc) ----------------
__device__ uint32_t g_h[(size_t)KK * NN * 32];   // h' = dis*(flatten@W1), bf16x2 packed
__device__ uint32_t g_x[(size_t)KK * NN * 32];   // relu(conv1), bf16x2 packed
__device__ int   g_deg[KK * NN];
__device__ float g_dis[KK * NN];
__device__ int   g_rowstart[KK * (NN + 1)];
__device__ int   g_cursor[KK * NN];
__device__ int   g_csrc[(size_t)KK * EE];
__device__ float g_h2[(size_t)KK * NN * 2];      // h2' = dis * (x @ w2eff + c0)
__device__ float g_gate[(size_t)NN * 4];
__device__ float g_sums[KK * HH];
__device__ float g_sumsq[KK * HH];
__device__ float g_w2eff[KK * HH * 2];
__device__ float g_c0[KK * 2];
__device__ int   g_partials[KK * CHUNKS];

// ---------------- helpers ----------------
__device__ __forceinline__ uint32_t f2tf(float f) {
    uint32_t u;
    asm("cvt.rna.tf32.f32 %0, %1;" : "=r"(u) : "f"(f));
    return u;
}
__device__ __forceinline__ uint32_t pack_bf2(float a, float b) {
    __nv_bfloat162 v = __floats2bfloat162_rn(a, b);
    return *(uint32_t*)&v;
}
__device__ __forceinline__ float2 unpack_bf2(uint32_t u) {
    __nv_bfloat162 v = *(__nv_bfloat162*)&u;
    return __bfloat1622float2(v);
}

// ---------------- init ----------------
__global__ void k_init() {
    int i = blockIdx.x * blockDim.x + threadIdx.x;
    if (i < KK * NN) g_deg[i] = 0;
    if (i < KK * HH) { g_sums[i] = 0.f; g_sumsq[i] = 0.f; }
    if (i < KK) g_rowstart[i * (NN + 1) + NN] = EE;
}

// ---------------- degree histogram (2 edges/thread) ----------------
__global__ void k_deg(const int* __restrict__ ei) {
    int k = blockIdx.y;
    int e = 2 * (blockIdx.x * blockDim.x + threadIdx.x);
    if (e >= EE) return;
    int2 d2 = *(const int2*)(ei + (size_t)k * 2 * EE + EE + e);
    atomicAdd(&g_deg[k * NN + d2.x], 1);
    atomicAdd(&g_deg[k * NN + d2.y], 1);
}

// ---------------- exclusive scan of deg (3 kernels) ----------------
__global__ void k_scanA() {
    int k = blockIdx.y, chunk = blockIdx.x, t = threadIdx.x;
    int n0 = chunk * 1024 + t * 4;
    int s = 0;
#pragma unroll
    for (int i = 0; i < 4; i++) { int n = n0 + i; if (n < NN) s += g_deg[k * NN + n]; }
    for (int off = 16; off; off >>= 1) s += __shfl_down_sync(0xffffffffu, s, off);
    __shared__ int ws[8];
    if ((t & 31) == 0) ws[t >> 5] = s;
    __syncthreads();
    if (t == 0) {
        int tot = 0;
        for (int i = 0; i < 8; i++) tot += ws[i];
        g_partials[k * CHUNKS + chunk] = tot;
    }
}

__global__ void k_scanB() {
    int t = threadIdx.x;  // 128
    __shared__ int sm[128];
    for (int k = 0; k < KK; k++) {
        int p = (t < CHUNKS) ? g_partials[k * CHUNKS + t] : 0;
        sm[t] = p; __syncthreads();
        for (int off = 1; off < 128; off <<= 1) {
            int a = (t >= off) ? sm[t - off] : 0;
            __syncthreads();
            sm[t] += a;
            __syncthreads();
        }
        if (t < CHUNKS) g_partials[k * CHUNKS + t] = sm[t] - p;  // exclusive
        __syncthreads();
    }
}

__global__ void k_scanC() {
    int k = blockIdx.y, chunk = blockIdx.x, t = threadIdx.x;
    int lane = t & 31, wid = t >> 5;
    int n0 = chunk * 1024 + t * 4;
    int v[4];
#pragma unroll
    for (int i = 0; i < 4; i++) { int n = n0 + i; v[i] = (n < NN) ? g_deg[k * NN + n] : 0; }
    int s0 = v[0], s1 = s0 + v[1], s2 = s1 + v[2], s3 = s2 + v[3];
    int x = s3;
    for (int off = 1; off < 32; off <<= 1) {
        int y = __shfl_up_sync(0xffffffffu, x, off);
        if (lane >= off) x += y;
    }
    __shared__ int ws[8];
    if (lane == 31) ws[wid] = x;
    __syncthreads();
    if (t < 8) {
        int w = ws[t];
        for (int off = 1; off < 8; off <<= 1) {
            int y = __shfl_up_sync(0xffu, w, off);
            if (t >= off) w += y;
        }
        ws[t] = w;
    }
    __syncthreads();
    int excl = ((wid == 0) ? 0 : ws[wid - 1]) + (x - s3);
    int gbase = g_partials[k * CHUNKS + chunk] + excl;
    int pre[4] = {0, s0, s1, s2};
#pragma unroll
    for (int i = 0; i < 4; i++) {
        int n = n0 + i;
        if (n < NN) {
            int rs = gbase + pre[i];
            g_rowstart[k * (NN + 1) + n] = rs;
            g_cursor[k * NN + n] = rs;
            g_dis[k * NN + n] = rsqrtf((float)v[i] + 2.0f);
        }
    }
}

// ---------------- GEMM1: h'[k] = dis[k] * (flatten @ W1[k])  (tf32 mma.sync) ----
#define ASTR 20
#define BSTR 264
__global__ __launch_bounds__(512) void k_gemm1(const float* __restrict__ A,
                                               const float* __restrict__ W1) {
    __shared__ uint32_t As[128 * ASTR];
    __shared__ uint32_t Bs[16 * BSTR];
    int t = threadIdx.x, lane = t & 31, warp = t >> 5;
    int wm = warp & 3, wn = warp >> 2;     // wn = expert index
    int bm = blockIdx.x;

    int ar = t >> 2, ac = (t & 3) * 4;
    int b0r = t >> 6,          b0q = (t & 63) * 4;
    int b1r = (t + 512) >> 6,  b1q = (t & 63) * 4;
    int b0k = b0q >> 6, b0h = b0q & 63;
    int b1k = b1q >> 6, b1h = b1q & 63;

    float4 rA, rB0, rB1;
    {
        int r0 = bm * 128 + ar;
        rA  = (r0 < NN) ? *(const float4*)(A + (size_t)r0 * FF + ac) : make_float4(0,0,0,0);
        rB0 = *(const float4*)(W1 + ((size_t)b0k * FF + b0r) * HH + b0h);
        rB1 = *(const float4*)(W1 + ((size_t)b1k * FF + b1r) * HH + b1h);
    }

    float c[2][8][4];
#pragma unroll
    for (int mi = 0; mi < 2; mi++)
#pragma unroll
        for (int ni = 0; ni < 8; ni++)
#pragma unroll
            for (int j = 0; j < 4; j++) c[mi][ni][j] = 0.f;

    for (int kt = 0; kt < 16; kt++) {
        As[ar * ASTR + ac + 0] = f2tf(rA.x);
        As[ar * ASTR + ac + 1] = f2tf(rA.y);
        As[ar * ASTR + ac + 2] = f2tf(rA.z);
        As[ar * ASTR + ac + 3] = f2tf(rA.w);
        Bs[b0r * BSTR + b0q + 0] = f2tf(rB0.x);
        Bs[b0r * BSTR + b0q + 1] = f2tf(rB0.y);
        Bs[b0r * BSTR + b0q + 2] = f2tf(rB0.z);
        Bs[b0r * BSTR + b0q + 3] = f2tf(rB0.w);
        Bs[b1r * BSTR + b1q + 0] = f2tf(rB1.x);
        Bs[b1r * BSTR + b1q + 1] = f2tf(rB1.y);
        Bs[b1r * BSTR + b1q + 2] = f2tf(rB1.z);
        Bs[b1r * BSTR + b1q + 3] = f2tf(rB1.w);
        __syncthreads();

        if (kt < 15) {
            int kn = (kt + 1) * 16;
            int r0 = bm * 128 + ar;
            rA  = (r0 < NN) ? *(const float4*)(A + (size_t)r0 * FF + kn + ac) : make_float4(0,0,0,0);
            rB0 = *(const float4*)(W1 + ((size_t)b0k * FF + kn + b0r) * HH + b0h);
            rB1 = *(const float4*)(W1 + ((size_t)b1k * FF + kn + b1r) * HH + b1h);
        }

#pragma unroll
        for (int kk = 0; kk < 16; kk += 8) {
            uint32_t af[2][4], bf[8][2];
#pragma unroll
            for (int mi = 0; mi < 2; mi++) {
                int r = wm * 32 + mi * 16 + (lane >> 2);
                int cc = kk + (lane & 3);
                af[mi][0] = As[r * ASTR + cc];
                af[mi][1] = As[(r + 8) * ASTR + cc];
                af[mi][2] = As[r * ASTR + cc + 4];
                af[mi][3] = As[(r + 8) * ASTR + cc + 4];
            }
#pragma unroll
            for (int ni = 0; ni < 8; ni++) {
                int col = wn * 64 + ni * 8 + (lane >> 2);
                int kr = kk + (lane & 3);
                bf[ni][0] = Bs[kr * BSTR + col];
                bf[ni][1] = Bs[(kr + 4) * BSTR + col];
            }
#pragma unroll
            for (int mi = 0; mi < 2; mi++)
#pragma unroll
                for (int ni = 0; ni < 8; ni++) {
                    asm volatile(
                        "mma.sync.aligned.m16n8k8.row.col.f32.tf32.tf32.f32 "
                        "{%0,%1,%2,%3}, {%4,%5,%6,%7}, {%8,%9}, {%0,%1,%2,%3};"
                        : "+f"(c[mi][ni][0]), "+f"(c[mi][ni][1]),
                          "+f"(c[mi][ni][2]), "+f"(c[mi][ni][3])
                        : "r"(af[mi][0]), "r"(af[mi][1]), "r"(af[mi][2]), "r"(af[mi][3]),
                          "r"(bf[ni][0]), "r"(bf[ni][1]));
                }
        }
        __syncthreads();
    }

    uint32_t* hk = g_h + (size_t)wn * NN * 32;
    const float* dk = g_dis + wn * NN;
#pragma unroll
    for (int mi = 0; mi < 2; mi++) {
        int r0 = bm * 128 + wm * 32 + mi * 16 + (lane >> 2);
        int r1 = r0 + 8;
        float s0 = (r0 < NN) ? dk[r0] : 0.f;
        float s1 = (r1 < NN) ? dk[r1] : 0.f;
#pragma unroll
        for (int ni = 0; ni < 8; ni++) {
            int w = ni * 4 + (lane & 3);
            if (r0 < NN) hk[(size_t)r0 * 32 + w] = pack_bf2(c[mi][ni][0] * s0, c[mi][ni][1] * s0);
            if (r1 < NN) hk[(size_t)r1 * 32 + w] = pack_bf2(c[mi][ni][2] * s1, c[mi][ni][3] * s1);
        }
    }
}

// ---------------- CSR fill (2 edges/thread) ----------------
__global__ void k_csr(const int* __restrict__ ei) {
    int k = blockIdx.y;
    int e = 2 * (blockIdx.x * blockDim.x + threadIdx.x);
    if (e >= EE) return;
    const int* base = ei + (size_t)k * 2 * EE;
    int2 s2v = *(const int2*)(base + e);
    int2 d2  = *(const int2*)(base + EE + e);
    int* csk = g_csrc + (size_t)k * EE;
    int p0 = atomicAdd(&g_cursor[k * NN + d2.x], 1);
    int p1 = atomicAdd(&g_cursor[k * NN + d2.y], 1);
    csk[p0] = s2v.x;
    csk[p1] = s2v.y;
}

// ------- conv1 aggregate + bias + relu -> x (bf16x2), fused LN stats -------
// 8 lanes per node; lane owns 8 features (uint4 = 4 bf16x2 words); 4-deep edge unroll.
__global__ __launch_bounds__(256) void k_agg1(const float* __restrict__ b1) {
    int k = blockIdx.y;
    int t = threadIdx.x, l8 = t & 7, sub = t >> 3;   // 32 subgroups of 8 lanes
    __shared__ float ss[64], sq[64];
    if (t < 64) { ss[t] = 0.f; sq[t] = 0.f; }
    __syncthreads();
    const uint32_t* hk = g_h + (size_t)k * NN * 32;
    const int* cs = g_csrc + (size_t)k * EE;
    const int* rs = g_rowstart + k * (NN + 1);
    const float* dk = g_dis + k * NN;
    int w0 = 4 * l8;
    float4 bva = *(const float4*)(b1 + k * HH + 8 * l8);
    float4 bvb = *(const float4*)(b1 + k * HH + 8 * l8 + 4);
    float ts[8], tq[8];
#pragma unroll
    for (int j = 0; j < 8; j++) { ts[j] = 0.f; tq[j] = 0.f; }

#pragma unroll
    for (int i = 0; i < 4; i++) {
        int node = blockIdx.x * 128 + sub * 4 + i;
        if (node >= NN) break;
        int base = rs[node], end = rs[node + 1];
        float a[8];
#pragma unroll
        for (int j = 0; j < 8; j++) a[j] = 0.f;
        int e = base;
        for (; e + 4 <= end; e += 4) {
            int i0 = __ldg(cs + e), i1 = __ldg(cs + e + 1);
            int i2 = __ldg(cs + e + 2), i3 = __ldg(cs + e + 3);
            uint4 r0 = *(const uint4*)(hk + (size_t)i0 * 32 + w0);
            uint4 r1 = *(const uint4*)(hk + (size_t)i1 * 32 + w0);
            uint4 r2 = *(const uint4*)(hk + (size_t)i2 * 32 + w0);
            uint4 r3 = *(const uint4*)(hk + (size_t)i3 * 32 + w0);
            float2 f;
            f = unpack_bf2(r0.x); a[0] += f.x; a[1] += f.y;
            f = unpack_bf2(r0.y); a[2] += f.x; a[3] += f.y;
            f = unpack_bf2(r0.z); a[4] += f.x; a[5] += f.y;
            f = unpack_bf2(r0.w); a[6] += f.x; a[7] += f.y;
            f = unpack_bf2(r1.x); a[0] += f.x; a[1] += f.y;
            f = unpack_bf2(r1.y); a[2] += f.x; a[3] += f.y;
            f = unpack_bf2(r1.z); a[4] += f.x; a[5] += f.y;
            f = unpack_bf2(r1.w); a[6] += f.x; a[7] += f.y;
            f = unpack_bf2(r2.x); a[0] += f.x; a[1] += f.y;
            f = unpack_bf2(r2.y); a[2] += f.x; a[3] += f.y;
            f = unpack_bf2(r2.z); a[4] += f.x; a[5] += f.y;
            f = unpack_bf2(r2.w); a[6] += f.x; a[7] += f.y;
            f = unpack_bf2(r3.x); a[0] += f.x; a[1] += f.y;
            f = unpack_bf2(r3.y); a[2] += f.x; a[3] += f.y;
            f = unpack_bf2(r3.z); a[4] += f.x; a[5] += f.y;
            f = unpack_bf2(r3.w); a[6] += f.x; a[7] += f.y;
        }
        for (; e < end; e++) {
            int s = __ldg(cs + e);
            uint4 r = *(const uint4*)(hk + (size_t)s * 32 + w0);
            float2 f;
            f = unpack_bf2(r.x); a[0] += f.x; a[1] += f.y;
            f = unpack_bf2(r.y); a[2] += f.x; a[3] += f.y;
            f = unpack_bf2(r.z); a[4] += f.x; a[5] += f.y;
            f = unpack_bf2(r.w); a[6] += f.x; a[7] += f.y;
        }
        float dn = dk[node];
        uint4 hn = *(const uint4*)(hk + (size_t)node * 32 + w0);
        float2 h0 = unpack_bf2(hn.x), h1 = unpack_bf2(hn.y);
        float2 h2v = unpack_bf2(hn.z), h3 = unpack_bf2(hn.w);
        float x0 = fmaxf(dn * (a[0] + 2.f * h0.x)  + bva.x, 0.f);
        float x1 = fmaxf(dn * (a[1] + 2.f * h0.y)  + bva.y, 0.f);
        float x2 = fmaxf(dn * (a[2] + 2.f * h1.x)  + bva.z, 0.f);
        float x3 = fmaxf(dn * (a[3] + 2.f * h1.y)  + bva.w, 0.f);
        float x4 = fmaxf(dn * (a[4] + 2.f * h2v.x) + bvb.x, 0.f);
        float x5 = fmaxf(dn * (a[5] + 2.f * h2v.y) + bvb.y, 0.f);
        float x6 = fmaxf(dn * (a[6] + 2.f * h3.x)  + bvb.z, 0.f);
        float x7 = fmaxf(dn * (a[7] + 2.f * h3.y)  + bvb.w, 0.f);
        *(uint4*)(g_x + ((size_t)k * NN + node) * 32 + w0) =
            make_uint4(pack_bf2(x0, x1), pack_bf2(x2, x3), pack_bf2(x4, x5), pack_bf2(x6, x7));
        ts[0] += x0; tq[0] += x0 * x0;
        ts[1] += x1; tq[1] += x1 * x1;
        ts[2] += x2; tq[2] += x2 * x2;
        ts[3] += x3; tq[3] += x3 * x3;
        ts[4] += x4; tq[4] += x4 * x4;
        ts[5] += x5; tq[5] += x5 * x5;
        ts[6] += x6; tq[6] += x6 * x6;
        ts[7] += x7; tq[7] += x7 * x7;
    }
#pragma unroll
    for (int j = 0; j < 8; j++) {
        atomicAdd(&ss[8 * l8 + j], ts[j]);
        atomicAdd(&sq[8 * l8 + j], tq[j]);
    }
    __syncthreads();
    if (t < 64) atomicAdd(&g_sums[k * HH + t], ss[t]);
    else if (t < 128) atomicAdd(&g_sumsq[k * HH + t - 64], sq[t - 64]);
}

// ---------------- fold LN into W2: w2eff = s*W2, c0 = t @ W2 ----------------
__global__ void k_lnfinal(const float* __restrict__ gamma, const float* __restrict__ beta,
                          const float* __restrict__ W2) {
    int t = threadIdx.x;  // 256
    int k = t >> 6, f = t & 63;
    float mu = g_sums[k * HH + f] / (float)NN;
    float var = g_sumsq[k * HH + f] / (float)NN - mu * mu;
    float inv = rsqrtf(var + 1e-5f);
    float s = inv * gamma[k * HH + f];
    float tt = beta[k * HH + f] - mu * s;
    float w0 = W2[k * HH * 2 + f * 2 + 0];
    float w1 = W2[k * HH * 2 + f * 2 + 1];
    g_w2eff[k * HH * 2 + f * 2 + 0] = s * w0;
    g_w2eff[k * HH * 2 + f * 2 + 1] = s * w1;
    __shared__ float red[256];
    red[t] = tt * w0; __syncthreads();
    for (int off = 32; off >= 1; off >>= 1) { if (f < off) red[t] += red[t + off]; __syncthreads(); }
    if (f == 0) g_c0[k * 2 + 0] = red[t];
    __syncthreads();
    red[t] = tt * w1; __syncthreads();
    for (int off = 32; off >= 1; off >>= 1) { if (f < off) red[t] += red[t + off]; __syncthreads(); }
    if (f == 0) g_c0[k * 2 + 1] = red[t];
}

// ---------------- h2' = dis * (relu_x @ w2eff + c0) ----------------
__global__ void k_h2() {
    int k = blockIdx.y;
    int t = threadIdx.x;
    __shared__ float w_s[128];
    __shared__ float c0s[2];
    if (t < 128) w_s[t] = g_w2eff[k * 128 + t];
    if (t < 2) c0s[t] = g_c0[k * 2 + t];
    __syncthreads();
    int n = blockIdx.x * blockDim.x + t;
    if (n >= NN) return;
    const uint32_t* xr = g_x + ((size_t)k * NN + n) * 32;
    float a0 = c0s[0], a1 = c0s[1];
#pragma unroll
    for (int w = 0; w < 32; w += 4) {
        uint4 q = *(const uint4*)(xr + w);
        float2 f0 = unpack_bf2(q.x), f1 = unpack_bf2(q.y);
        float2 f2 = unpack_bf2(q.z), f3 = unpack_bf2(q.w);
        a0 += f0.x * w_s[4*w]      + f0.y * w_s[4*w + 2]
            + f1.x * w_s[4*w + 4]  + f1.y * w_s[4*w + 6]
            + f2.x * w_s[4*w + 8]  + f2.y * w_s[4*w + 10]
            + f3.x * w_s[4*w + 12] + f3.y * w_s[4*w + 14];
        a1 += f0.x * w_s[4*w + 1]  + f0.y * w_s[4*w + 3]
            + f1.x * w_s[4*w + 5]  + f1.y * w_s[4*w + 7]
            + f2.x * w_s[4*w + 9]  + f2.y * w_s[4*w + 11]
            + f3.x * w_s[4*w + 13] + f3.y * w_s[4*w + 15];
    }
    float dn = g_dis[k * NN + n];
    g_h2[((size_t)k * NN + n) * 2 + 0] = a0 * dn;
    g_h2[((size_t)k * NN + n) * 2 + 1] = a1 * dn;
}

// ---------------- gating weights (independent; runs early on stream 2) ----------
__global__ __launch_bounds__(256) void k_gate(const float* __restrict__ mf,
                                              const float* __restrict__ Wg,
                                              const float* __restrict__ bg) {
    __shared__ float wg_s[FF * KK];
    __shared__ float bg_s[KK];
    int t = threadIdx.x;
    for (int i = t; i < FF * KK; i += 256) wg_s[i] = Wg[i];
    if (t < KK) bg_s[t] = bg[t];
    __syncthreads();
    int lane = t & 31;
    int node = blockIdx.x * 8 + (t >> 5);
    if (node >= NN) return;
    const float* row = mf + (size_t)node * FF;
    float a0 = 0.f, a1 = 0.f, a2 = 0.f, a3 = 0.f;
#pragma unroll
    for (int j = 0; j < 8; j++) {
        float v = row[lane + 32 * j];
        const float* w = &wg_s[(lane + 32 * j) * 4];
        a0 += v * w[0]; a1 += v * w[1]; a2 += v * w[2]; a3 += v * w[3];
    }
    for (int off = 16; off; off >>= 1) {
        a0 += __shfl_xor_sync(0xffffffffu, a0, off);
        a1 += __shfl_xor_sync(0xffffffffu, a1, off);
        a2 += __shfl_xor_sync(0xffffffffu, a2, off);
        a3 += __shfl_xor_sync(0xffffffffu, a3, off);
    }
    if (lane == 0) {
        float l0 = a0 + bg_s[0], l1 = a1 + bg_s[1], l2 = a2 + bg_s[2], l3 = a3 + bg_s[3];
        float m = fmaxf(fmaxf(l0, l1), fmaxf(l2, l3));
        float e0 = expf(l0 - m), e1 = expf(l1 - m), e2 = expf(l2 - m), e3 = expf(l3 - m);
        float Z = 1.f / (e0 + e1 + e2 + e3);
        *(float4*)(g_gate + (size_t)node * 4) = make_float4(e0 * Z, e1 * Z, e2 * Z, e3 * Z);
    }
}

// ---------------- conv2 aggregate + gating mix -> out (fused) ----------------
__global__ void k_agg2f(const float* __restrict__ b2, float* __restrict__ out) {
    int n = blockIdx.x * blockDim.x + threadIdx.x;
    if (n >= NN) return;
    float la[KK], lb[KK];
#pragma unroll
    for (int k = 0; k < KK; k++) {
        int base = g_rowstart[k * (NN + 1) + n];
        int end  = g_rowstart[k * (NN + 1) + n + 1];
        const int* cs = g_csrc + (size_t)k * EE;
        const float2* h2k = (const float2*)(g_h2 + (size_t)k * NN * 2);
        float a0 = 0.f, a1 = 0.f;
        int e = base;
        for (; e + 4 <= end; e += 4) {
            int i0 = __ldg(cs + e), i1 = __ldg(cs + e + 1);
            int i2 = __ldg(cs + e + 2), i3 = __ldg(cs + e + 3);
            float2 v0 = h2k[i0], v1 = h2k[i1], v2 = h2k[i2], v3 = h2k[i3];
            a0 += v0.x + v1.x + v2.x + v3.x;
            a1 += v0.y + v1.y + v2.y + v3.y;
        }
        for (; e < end; e++) {
            float2 hv = h2k[__ldg(cs + e)];
            a0 += hv.x;
            a1 += hv.y;
        }
        float dn = g_dis[k * NN + n];
        float2 hn = h2k[n];
        la[k] = dn * (a0 + 2.f * hn.x) + __ldg(b2 + k * 2 + 0);
        lb[k] = dn * (a1 + 2.f * hn.y) + __ldg(b2 + k * 2 + 1);
    }
    float4 wv = *(const float4*)(g_gate + (size_t)n * 4);
    float wk[4] = {wv.x, wv.y, wv.z, wv.w};
    float r0 = 0.f, r1 = 0.f, p0 = 0.f, p1 = 0.f;
#pragma unroll
    for (int k = 0; k < KK; k++) {
        float mm = fmaxf(la[k], lb[k]);
        float ea = expf(la[k] - mm), eb = expf(lb[k] - mm);
        float z = ea + eb;
        float lse = mm + logf(z);
        r0 += wk[k] * (la[k] - lse);
        r1 += wk[k] * (lb[k] - lse);
        p0 += wk[k] * (ea / z);
        p1 += wk[k] * (eb / z);
    }
    out[(size_t)n * 2 + 0] = r0;
    out[(size_t)n * 2 + 1] = r1;
    out[(size_t)2 * NN + n * 2 + 0] = p0;
    out[(size_t)2 * NN + n * 2 + 1] = p1;
}

// ---------------- launch ----------------
static cudaStream_t s2 = nullptr;
static cudaEvent_t ev0 = nullptr, evC = nullptr, evG = nullptr;

extern "C" void kernel_launch(void* const* d_in, const int* in_sizes, int n_in,
                              void* d_out, int out_size) {
    const float* flatten = (const float*)d_in[0];
    const float* moe     = (const float*)d_in[1];
    const int*   ei      = (const int*)d_in[2];
    const float* W1      = (const float*)d_in[3];
    const float* b1      = (const float*)d_in[4];
    const float* gamma   = (const float*)d_in[5];
    const float* beta    = (const float*)d_in[6];
    const float* W2      = (const float*)d_in[7];
    const float* b2      = (const float*)d_in[8];
    const float* Wg      = (const float*)d_in[9];
    const float* bg      = (const float*)d_in[10];
    float* out = (float*)d_out;

    if (s2 == nullptr) {
        cudaStreamCreateWithFlags(&s2, cudaStreamNonBlocking);
        cudaEventCreateWithFlags(&ev0, cudaEventDisableTiming);
        cudaEventCreateWithFlags(&evC, cudaEventDisableTiming);
        cudaEventCreateWithFlags(&evG, cudaEventDisableTiming);
    }

    // main stream (legacy default)
    k_init<<<(KK * NN + 255) / 256, 256>>>();
    cudaEventRecord(ev0, 0);

    // side stream: gating GEMV (independent), later GEMM1
    cudaStreamWaitEvent(s2, ev0, 0);
    k_gate<<<(NN + 7) / 8, 256, 0, s2>>>(moe, Wg, bg);

    k_deg<<<dim3((EE / 2 + 255) / 256, KK), 256>>>(ei);
    k_scanA<<<dim3(CHUNKS, KK), 256>>>();
    k_scanB<<<1, 128>>>();
    k_scanC<<<dim3(CHUNKS, KK), 256>>>();
    cudaEventRecord(evC, 0);

    // GEMM1 needs g_dis (scanC); runs concurrent with CSR fill
    cudaStreamWaitEvent(s2, evC, 0);
    k_gemm1<<<dim3((NN + 127) / 128), 512, 0, s2>>>(flatten, W1);
    cudaEventRecord(evG, s2);

    k_csr<<<dim3((EE / 2 + 255) / 256, KK), 256>>>(ei);

    cudaStreamWaitEvent(0, evG, 0);   // join: agg1 needs g_h + g_csrc
    k_agg1<<<dim3((NN + 127) / 128, KK), 256>>>(b1);
    k_lnfinal<<<1, 256>>>(gamma, beta, W2);
    k_h2<<<dim3((NN + 255) / 256, KK), 256>>>();
    k_agg2f<<<(NN + 255) / 256, 256>>>(b2, out);
}